// round 16
// baseline (speedup 1.0000x reference)
#include <cuda_runtime.h>
#include <cuda_fp16.h>
#include <cstdint>
#include <math.h>

// ---------------- problem constants ----------------
#define D_MODEL 256
#define NH 8
#define HD 32
#define NL 4
#define NP 4
#define DFF 1024
#define B_SZ 2
#define LT 20
#define LQ_C 20197
#define NTOK (B_SZ * LQ_C)   // 40394

__device__ __constant__ int c_H[NL]  = {100, 50, 25, 13};
__device__ __constant__ int c_W[NL]  = {152, 76, 38, 19};
__device__ __constant__ int c_St[NL] = {0, 15200, 19000, 19950};

// ---------------- scratch (static device globals; no allocation) ----------------
__device__ float g_offs[NTOK * D_MODEL];
__device__ float g_aw[NTOK * 128];
__device__ __half g_q[NTOK * D_MODEL];
__device__ __half g_kh[B_SZ * LT * D_MODEL];
__device__ __half g_vh[B_SZ * LT * D_MODEL];
__device__ __half g_val[NTOK * D_MODEL];
__device__ __half g_A[NTOK * D_MODEL];
__device__ __half g_B[NTOK * D_MODEL];
__device__ __half g_hid[NTOK * DFF];
__device__ __half g_vpw[65536];
__device__ __half g_sow[65536];
__device__ __half g_aww[32768];
__device__ __half g_opw[65536];
__device__ __half g_wqw[65536];
__device__ __half g_mow[65536];
__device__ __half g_l1w[262144];
__device__ __half g_l2w[262144];

static inline int cdiv(int a, int b) { return (a + b - 1) / b; }

__device__ __forceinline__ uint32_t smem_u32(const void* p) {
    uint32_t a;
    asm("{ .reg .u64 t; cvta.to.shared.u64 t, %1; cvt.u32.u64 %0, t; }" : "=r"(a) : "l"(p));
    return a;
}
__device__ __forceinline__ void ldm_x4(uint32_t addr, uint32_t& r0, uint32_t& r1,
                                       uint32_t& r2, uint32_t& r3) {
    asm volatile("ldmatrix.sync.aligned.m8n8.x4.shared.b16 {%0,%1,%2,%3}, [%4];"
                 : "=r"(r0), "=r"(r1), "=r"(r2), "=r"(r3) : "r"(addr));
}
__device__ __forceinline__ void mma_f16(float* c, const uint32_t* a, const uint32_t* b) {
    asm volatile(
        "mma.sync.aligned.m16n8k16.row.col.f32.f16.f16.f32 "
        "{%0,%1,%2,%3}, {%4,%5,%6,%7}, {%8,%9}, {%0,%1,%2,%3};"
        : "+f"(c[0]), "+f"(c[1]), "+f"(c[2]), "+f"(c[3])
        : "r"(a[0]), "r"(a[1]), "r"(a[2]), "r"(a[3]), "r"(b[0]), "r"(b[1]));
}
__device__ __forceinline__ uint2 f4_to_h4(float4 v) {
    union { __half2 h2[2]; uint2 u; } U;
    U.h2[0] = __floats2half2_rn(v.x, v.y);
    U.h2[1] = __floats2half2_rn(v.z, v.w);
    return U.u;
}
__device__ __forceinline__ void cpa16(uint32_t dst, const void* src) {
    asm volatile("cp.async.cg.shared.global [%0], [%1], 16;" :: "r"(dst), "l"(src));
}
__device__ __forceinline__ void cpa16z(uint32_t dst, const void* src, bool v) {
    int sz = v ? 16 : 0;
    asm volatile("cp.async.cg.shared.global [%0], [%1], 16, %2;"
                 :: "r"(dst), "l"(src), "r"(sz));
}

#define KC 64
#define A_TILE_B 8192
#define B_TILE_B 16384
#define STAGE_B (A_TILE_B + B_TILE_B)   // 24 KB
#define GEMM_SMEM (2 * STAGE_B)         // 48 KB -> 4 CTAs/SM

// =====================================================================
// GEMM mainloop core (CTA 64x128, 256 thr, warp 32x32, KC=64, 2 stages,
// 2 syncs/chunk). Produces acc[2][4][4] for this CTA's 64x128 tile.
// =====================================================================
struct GemmCore {
    float acc[2][4][4];

    __device__ __forceinline__ void run(uint32_t sbase, const __half* Aop, const __half* bW,
                                        int rowBase, int M, int K,
                                        int tid, int wid, int lane) {
        const int warpM = wid >> 2;
        const int warpN = wid & 3;
#pragma unroll
        for (int mi = 0; mi < 2; mi++)
#pragma unroll
            for (int ni = 0; ni < 4; ni++)
#pragma unroll
                for (int j = 0; j < 4; j++) acc[mi][ni][j] = 0.f;

        const uint32_t swX = (uint32_t)((lane & 7) << 4);
        const int aKB0 = (lane >> 4) * 16;
        uint32_t aRowOff[2];
#pragma unroll
        for (int mi = 0; mi < 2; mi++)
            aRowOff[mi] = (uint32_t)((warpM * 32 + mi * 16 + (lane & 15)) * 128);
        const int grp = lane >> 3;
        const int bKB0 = (grp & 1) * 16;
        uint32_t bRowOff[2];
#pragma unroll
        for (int np = 0; np < 2; np++)
            bRowOff[np] = (uint32_t)((warpN * 32 + np * 16 + ((grp >> 1) << 3) + (lane & 7)) * 128);

        const int nChunks = K / KC;
        auto copy_chunk = [&](int kt, uint32_t stg) {
            const int k0 = kt * KC;
#pragma unroll
            for (int i = 0; i < 4; i++) {
                int idx = tid + i * 256;
                int r = idx >> 3, c = idx & 7;
                uint32_t off = (uint32_t)(r * 128 + ((c * 16) ^ ((r & 7) << 4)));
                cpa16(stg + A_TILE_B + off, bW + (size_t)r * K + k0 + c * 8);
            }
#pragma unroll
            for (int i = 0; i < 2; i++) {
                int idx = tid + i * 256;
                int r = idx >> 3, c = idx & 7;
                uint32_t off = (uint32_t)(r * 128 + ((c * 16) ^ ((r & 7) << 4)));
                int gr = rowBase + r;
                bool v = gr < M;
                int crr = v ? gr : (M - 1);
                cpa16z(stg + off, Aop + (size_t)crr * K + k0 + c * 8, v);
            }
        };

        copy_chunk(0, sbase);
        asm volatile("cp.async.commit_group;");
        for (int kt = 0; kt < nChunks; kt++) {
            if (kt + 1 < nChunks) {
                copy_chunk(kt + 1, sbase + (uint32_t)(((kt + 1) & 1) * STAGE_B));
                asm volatile("cp.async.commit_group;");
                asm volatile("cp.async.wait_group 1;");
            } else {
                asm volatile("cp.async.wait_group 0;");
            }
            __syncthreads();
            const uint32_t AS = sbase + (uint32_t)((kt & 1) * STAGE_B);
            const uint32_t BS = AS + A_TILE_B;
#pragma unroll
            for (int kst = 0; kst < 4; kst++) {
                uint32_t a[2][4];
#pragma unroll
                for (int mi = 0; mi < 2; mi++) {
                    uint32_t kb = (uint32_t)(aKB0 + kst * 32);
                    ldm_x4(AS + aRowOff[mi] + (kb ^ swX),
                           a[mi][0], a[mi][1], a[mi][2], a[mi][3]);
                }
                uint32_t b[4][2];
#pragma unroll
                for (int np = 0; np < 2; np++) {
                    uint32_t kb = (uint32_t)(bKB0 + kst * 32);
                    uint32_t r0, r1, r2, r3;
                    ldm_x4(BS + bRowOff[np] + (kb ^ swX), r0, r1, r2, r3);
                    b[np * 2][0] = r0; b[np * 2][1] = r1;
                    b[np * 2 + 1][0] = r2; b[np * 2 + 1][1] = r3;
                }
#pragma unroll
                for (int mi = 0; mi < 2; mi++)
#pragma unroll
                    for (int ni = 0; ni < 4; ni++) mma_f16(acc[mi][ni], a[mi], b[ni]);
            }
            if (kt + 1 < nChunks) __syncthreads();
        }
    }
};

// =====================================================================
// tc_gemm: MODE 0: +bias  2: +bias,relu.  OH: half output.  4 CTAs/SM.
// =====================================================================
template <int MODE, bool OH>
__global__ void __launch_bounds__(256, 4)
tc_gemm(const __half* __restrict__ A, const __half* __restrict__ W,
        const float* __restrict__ bias, float* __restrict__ C,
        int M, int N, int K) {
    extern __shared__ char smem[];
    const uint32_t sbase = smem_u32(smem);
    const int tid = threadIdx.x;
    const int wid = tid >> 5;
    const int lane = tid & 31;
    const int rowBase = blockIdx.y * 64;
    const int colBase = blockIdx.x * 128;
    const int warpM = wid >> 2;
    const int warpN = wid & 3;

    GemmCore gc;
    gc.run(sbase, A, W + (size_t)colBase * K, rowBase, M, K, tid, wid, lane);

    const int qrow = lane >> 2;
    const int qcol = (lane & 3) * 2;
#pragma unroll
    for (int ni = 0; ni < 4; ni++) {
        int col = colBase + warpN * 32 + ni * 8 + qcol;
        float b0 = __ldg(bias + col), b1 = __ldg(bias + col + 1);
#pragma unroll
        for (int mi = 0; mi < 2; mi++) {
            gc.acc[mi][ni][0] += b0; gc.acc[mi][ni][1] += b1;
            gc.acc[mi][ni][2] += b0; gc.acc[mi][ni][3] += b1;
        }
    }
#pragma unroll
    for (int mi = 0; mi < 2; mi++)
#pragma unroll
        for (int rh = 0; rh < 2; rh++) {
            int row = rowBase + warpM * 32 + mi * 16 + qrow + rh * 8;
            if (row >= M) continue;
#pragma unroll
            for (int ni = 0; ni < 4; ni++) {
                int col = colBase + warpN * 32 + ni * 8 + qcol;
                float v0 = gc.acc[mi][ni][rh * 2], v1 = gc.acc[mi][ni][rh * 2 + 1];
                if (MODE == 2) { v0 = fmaxf(v0, 0.f); v1 = fmaxf(v1, 0.f); }
                if (OH)
                    *(__half2*)((__half*)C + (size_t)row * N + col) = __floats2half2_rn(v0, v1);
                else
                    *(float2*)(C + (size_t)row * N + col) = make_float2(v0, v1);
            }
        }
}

// =====================================================================
// tc_gemm_head: fused head GEMMs. grid (5, mTiles). 4 CTAs/SM.
//   x 0,1: val = src @ vp^T + b      (half out)
//   x 2,3: offs = q  @ so^T + b      (f32 out)
//   x 4:   aw = softmax16(q @ aw^T + b)
// =====================================================================
__global__ void __launch_bounds__(256, 4)
tc_gemm_head(const __half* __restrict__ Asrc, const __half* __restrict__ Aq,
             const __half* __restrict__ Wvp, const __half* __restrict__ Wso,
             const __half* __restrict__ Waw,
             const float* __restrict__ vp_b, const float* __restrict__ so_b,
             const float* __restrict__ aw_b,
             __half* __restrict__ val, float* __restrict__ offs, float* __restrict__ aw,
             int M) {
    extern __shared__ char smem[];
    const uint32_t sbase = smem_u32(smem);
    const int tid = threadIdx.x;
    const int wid = tid >> 5;
    const int lane = tid & 31;
    const int rowBase = blockIdx.y * 64;
    const int bx = blockIdx.x;
    const int warpM = wid >> 2;
    const int warpN = wid & 3;
    const int K = 256;

    int mode, colBase;
    const __half* Aop;
    const __half* Wop;
    const float* bp;
    if (bx < 2) { mode = 0; colBase = bx * 128; Aop = Asrc; Wop = Wvp; bp = vp_b; }
    else if (bx < 4) { mode = 1; colBase = (bx - 2) * 128; Aop = Aq; Wop = Wso; bp = so_b; }
    else { mode = 2; colBase = 0; Aop = Aq; Wop = Waw; bp = aw_b; }

    GemmCore gc;
    gc.run(sbase, Aop, Wop + (size_t)colBase * K, rowBase, M, K, tid, wid, lane);

    const int qrow = lane >> 2;
    const int qcol = (lane & 3) * 2;
#pragma unroll
    for (int ni = 0; ni < 4; ni++) {
        int col = colBase + warpN * 32 + ni * 8 + qcol;
        float b0 = __ldg(bp + col), b1 = __ldg(bp + col + 1);
#pragma unroll
        for (int mi = 0; mi < 2; mi++) {
            gc.acc[mi][ni][0] += b0; gc.acc[mi][ni][1] += b1;
            gc.acc[mi][ni][2] += b0; gc.acc[mi][ni][3] += b1;
        }
    }
    if (mode == 2) {
#pragma unroll
        for (int mi = 0; mi < 2; mi++)
#pragma unroll
            for (int g = 0; g < 2; g++)
#pragma unroll
                for (int rh = 0; rh < 2; rh++) {
                    float v0 = gc.acc[mi][2 * g][rh * 2], v1 = gc.acc[mi][2 * g][rh * 2 + 1];
                    float v2 = gc.acc[mi][2 * g + 1][rh * 2], v3 = gc.acc[mi][2 * g + 1][rh * 2 + 1];
                    float mx = fmaxf(fmaxf(v0, v1), fmaxf(v2, v3));
                    mx = fmaxf(mx, __shfl_xor_sync(0xffffffffu, mx, 1));
                    mx = fmaxf(mx, __shfl_xor_sync(0xffffffffu, mx, 2));
                    v0 = expf(v0 - mx); v1 = expf(v1 - mx);
                    v2 = expf(v2 - mx); v3 = expf(v3 - mx);
                    float s = v0 + v1 + v2 + v3;
                    s += __shfl_xor_sync(0xffffffffu, s, 1);
                    s += __shfl_xor_sync(0xffffffffu, s, 2);
                    float inv = 1.f / s;
                    gc.acc[mi][2 * g][rh * 2] = v0 * inv;
                    gc.acc[mi][2 * g][rh * 2 + 1] = v1 * inv;
                    gc.acc[mi][2 * g + 1][rh * 2] = v2 * inv;
                    gc.acc[mi][2 * g + 1][rh * 2 + 1] = v3 * inv;
                }
    }
#pragma unroll
    for (int mi = 0; mi < 2; mi++)
#pragma unroll
        for (int rh = 0; rh < 2; rh++) {
            int row = rowBase + warpM * 32 + mi * 16 + qrow + rh * 8;
            if (row >= M) continue;
#pragma unroll
            for (int ni = 0; ni < 4; ni++) {
                int cl_ = warpN * 32 + ni * 8 + qcol;
                float v0 = gc.acc[mi][ni][rh * 2], v1 = gc.acc[mi][ni][rh * 2 + 1];
                if (mode == 0) {
                    *(__half2*)(val + (size_t)row * 256 + colBase + cl_) =
                        __floats2half2_rn(v0, v1);
                } else if (mode == 1) {
                    *(float2*)(offs + (size_t)row * 256 + colBase + cl_) = make_float2(v0, v1);
                } else {
                    *(float2*)(aw + (size_t)row * 128 + cl_) = make_float2(v0, v1);
                }
            }
        }
}

// =====================================================================
// tc_gemm_ln: fp16 GEMM + residual + fused LayerNorm. CTA 64x256 (full rows),
//   8 warps (warp tile 32x64), KC=64, 2 stages (40 KB each), 2 CTAs/SM.
// =====================================================================
#define LA_TILE_B 8192
#define LB_TILE_B 32768
#define LSTAGE_B (LA_TILE_B + LB_TILE_B)
#define GEMM_LN_SMEM (2 * LSTAGE_B)     // 80 KB

template <bool WANTH, bool HASP>
__global__ void __launch_bounds__(256, 2)
tc_gemm_ln(const __half* __restrict__ A, const __half* __restrict__ W,
           const float* __restrict__ bias, const float* __restrict__ R,
           const float* __restrict__ lng, const float* __restrict__ lnb,
           const float* __restrict__ P, float* __restrict__ Cout,
           __half* __restrict__ Sh, int M, int K) {
    extern __shared__ char smem[];
    const uint32_t sbase = smem_u32(smem);
    const int tid = threadIdx.x;
    const int wid = tid >> 5;
    const int lane = tid & 31;
    const int rowBase = blockIdx.x * 64;
    const int warpM = wid >> 2;
    const int warpN = wid & 3;

    float acc[2][8][4];
#pragma unroll
    for (int mi = 0; mi < 2; mi++)
#pragma unroll
        for (int ni = 0; ni < 8; ni++)
#pragma unroll
            for (int j = 0; j < 4; j++) acc[mi][ni][j] = 0.f;

    const uint32_t swX = (uint32_t)((lane & 7) << 4);
    const int aKB0 = (lane >> 4) * 16;
    uint32_t aRowOff[2];
#pragma unroll
    for (int mi = 0; mi < 2; mi++)
        aRowOff[mi] = (uint32_t)((warpM * 32 + mi * 16 + (lane & 15)) * 128);
    const int grp = lane >> 3;
    const int bKB0 = (grp & 1) * 16;
    uint32_t bRowOff[4];
#pragma unroll
    for (int np = 0; np < 4; np++)
        bRowOff[np] = (uint32_t)((warpN * 64 + np * 16 + ((grp >> 1) << 3) + (lane & 7)) * 128);

    const int nChunks = K / KC;

    auto copy_chunk = [&](int kt, uint32_t stg) {
        const int k0 = kt * KC;
#pragma unroll
        for (int i = 0; i < 8; i++) {
            int idx = tid + i * 256;
            int r = idx >> 3, c = idx & 7;
            uint32_t off = (uint32_t)(r * 128 + ((c * 16) ^ ((r & 7) << 4)));
            cpa16(stg + LA_TILE_B + off, W + (size_t)r * K + k0 + c * 8);
        }
#pragma unroll
        for (int i = 0; i < 2; i++) {
            int idx = tid + i * 256;
            int r = idx >> 3, c = idx & 7;
            uint32_t off = (uint32_t)(r * 128 + ((c * 16) ^ ((r & 7) << 4)));
            int gr = rowBase + r;
            bool v = gr < M;
            int crr = v ? gr : (M - 1);
            cpa16z(stg + off, A + (size_t)crr * K + k0 + c * 8, v);
        }
    };

    copy_chunk(0, sbase);
    asm volatile("cp.async.commit_group;");
    for (int kt = 0; kt < nChunks; kt++) {
        if (kt + 1 < nChunks) {
            copy_chunk(kt + 1, sbase + (uint32_t)(((kt + 1) & 1) * LSTAGE_B));
            asm volatile("cp.async.commit_group;");
            asm volatile("cp.async.wait_group 1;");
        } else {
            asm volatile("cp.async.wait_group 0;");
        }
        __syncthreads();
        const uint32_t AS = sbase + (uint32_t)((kt & 1) * LSTAGE_B);
        const uint32_t BS = AS + LA_TILE_B;
#pragma unroll
        for (int kst = 0; kst < 4; kst++) {
            uint32_t a[2][4];
#pragma unroll
            for (int mi = 0; mi < 2; mi++) {
                uint32_t kb = (uint32_t)(aKB0 + kst * 32);
                ldm_x4(AS + aRowOff[mi] + (kb ^ swX), a[mi][0], a[mi][1], a[mi][2], a[mi][3]);
            }
#pragma unroll
            for (int np = 0; np < 4; np++) {
                uint32_t kb = (uint32_t)(bKB0 + kst * 32);
                uint32_t r0, r1, r2, r3;
                ldm_x4(BS + bRowOff[np] + (kb ^ swX), r0, r1, r2, r3);
                uint32_t b0[2] = {r0, r1}, b1[2] = {r2, r3};
#pragma unroll
                for (int mi = 0; mi < 2; mi++) {
                    mma_f16(acc[mi][2 * np], a[mi], b0);
                    mma_f16(acc[mi][2 * np + 1], a[mi], b1);
                }
            }
        }
        if (kt + 1 < nChunks) __syncthreads();
    }

    // ---- fused epilogue: bias + residual + LayerNorm ----
    __syncthreads();
    float* red = (float*)smem;
    const int qrow = lane >> 2;
    const int qcol = (lane & 3) * 2;

#pragma unroll
    for (int mi = 0; mi < 2; mi++)
#pragma unroll
        for (int rh = 0; rh < 2; rh++) {
            int rloc = warpM * 32 + mi * 16 + rh * 8 + qrow;
            int row = rowBase + rloc;
            bool ok = row < M;
            float s = 0.f, qsum = 0.f;
#pragma unroll
            for (int ni = 0; ni < 8; ni++) {
                int col = warpN * 64 + ni * 8 + qcol;
                float b0 = __ldg(bias + col), b1 = __ldg(bias + col + 1);
                float v0 = acc[mi][ni][rh * 2] + b0;
                float v1 = acc[mi][ni][rh * 2 + 1] + b1;
                if (ok) {
                    const float2 rr = *(const float2*)(R + (size_t)row * 256 + col);
                    v0 += rr.x; v1 += rr.y;
                }
                acc[mi][ni][rh * 2] = v0;
                acc[mi][ni][rh * 2 + 1] = v1;
                s += v0 + v1;
                qsum += v0 * v0 + v1 * v1;
            }
            s += __shfl_xor_sync(0xffffffffu, s, 1);
            s += __shfl_xor_sync(0xffffffffu, s, 2);
            qsum += __shfl_xor_sync(0xffffffffu, qsum, 1);
            qsum += __shfl_xor_sync(0xffffffffu, qsum, 2);
            if ((lane & 3) == 0) {
                red[(rloc << 3) + (warpN << 1)] = s;
                red[(rloc << 3) + (warpN << 1) + 1] = qsum;
            }
        }
    __syncthreads();
#pragma unroll
    for (int mi = 0; mi < 2; mi++)
#pragma unroll
        for (int rh = 0; rh < 2; rh++) {
            int rloc = warpM * 32 + mi * 16 + rh * 8 + qrow;
            int row = rowBase + rloc;
            if (row >= M) continue;
            float s = red[(rloc << 3)] + red[(rloc << 3) + 2] +
                      red[(rloc << 3) + 4] + red[(rloc << 3) + 6];
            float qsum = red[(rloc << 3) + 1] + red[(rloc << 3) + 3] +
                         red[(rloc << 3) + 5] + red[(rloc << 3) + 7];
            float mean = s * (1.f / 256.f);
            float var = qsum * (1.f / 256.f) - mean * mean;
            float rstd = rsqrtf(var + 1e-5f);
#pragma unroll
            for (int ni = 0; ni < 8; ni++) {
                int col = warpN * 64 + ni * 8 + qcol;
                float g0 = __ldg(lng + col), g1 = __ldg(lng + col + 1);
                float c0 = __ldg(lnb + col), c1 = __ldg(lnb + col + 1);
                float y0 = (acc[mi][ni][rh * 2] - mean) * rstd * g0 + c0;
                float y1 = (acc[mi][ni][rh * 2 + 1] - mean) * rstd * g1 + c1;
                *(float2*)(Cout + (size_t)row * 256 + col) = make_float2(y0, y1);
                if (WANTH) {
                    float t0 = y0, t1 = y1;
                    if (HASP) {
                        const float2 pp = *(const float2*)(P + (size_t)row * 256 + col);
                        t0 += pp.x; t1 += pp.y;
                    }
                    *(__half2*)(Sh + (size_t)row * 256 + col) = __floats2half2_rn(t0, t1);
                }
            }
        }
}

// ---------------- batched weight conversion (fp32 -> fp16) ----------------
struct WJob { const float* s; __half* h; int n4; };
struct WJobs { WJob j[8]; };
__global__ void wconv_kernel(WJobs J) {
    int i = blockIdx.x * blockDim.x + threadIdx.x;
#pragma unroll
    for (int k = 0; k < 8; k++) {
        int n = J.j[k].n4;
        if (i < n) {
            ((uint2*)J.j[k].h)[i] = f4_to_h4(((const float4*)J.j[k].s)[i]);
            return;
        }
        i -= n;
    }
}
__global__ void actconv_kernel(const float* __restrict__ src, const float* __restrict__ pos,
                               __half* __restrict__ A, __half* __restrict__ B, int n4) {
    int i = blockIdx.x * blockDim.x + threadIdx.x;
    if (i >= n4) return;
    float4 s = ((const float4*)src)[i];
    float4 p = ((const float4*)pos)[i];
    ((uint2*)A)[i] = f4_to_h4(s);
    s.x += p.x; s.y += p.y; s.z += p.z; s.w += p.w;
    ((uint2*)B)[i] = f4_to_h4(s);
}

// ---------------- multi-scale deformable sampling ----------------
__global__ void msdeform_kernel(const __half* __restrict__ value, const float* __restrict__ offs,
                                const float* __restrict__ aw, const float* __restrict__ ref,
                                __half* __restrict__ outh) {
    int gw = (blockIdx.x * blockDim.x + threadIdx.x) >> 5;
    int lane = threadIdx.x & 31;
    if (gw >= NTOK * NH) return;
    int token = gw >> 3, h = gw & 7;
    int b = (token >= LQ_C) ? 1 : 0;

    int p = lane & 15;
    int l = p >> 2;
    int Wl = c_W[l], Hl = c_H[l];
    float Wf = (float)Wl, Hf = (float)Hl;
    float rx = __ldg(ref + (size_t)token * 8 + l * 2);
    float ry = __ldg(ref + (size_t)token * 8 + l * 2 + 1);
    float ox = __ldg(offs + (size_t)token * 256 + h * 32 + p * 2);
    float oy = __ldg(offs + (size_t)token * 256 + h * 32 + p * 2 + 1);
    float wA = __ldg(aw + (size_t)token * 128 + h * 16 + p);

    float X = (rx + ox / Wf) * Wf - 0.5f;
    float Y = (ry + oy / Hf) * Hf - 0.5f;
    float x0f = floorf(X), y0f = floorf(Y);
    float lx = X - x0f, ly = Y - y0f;
    int x0 = (int)x0f, y0 = (int)y0f;
    int x1 = x0 + 1, y1 = y0 + 1;
    bool vx0 = (x0 >= 0) & (x0 < Wl), vx1 = (x1 >= 0) & (x1 < Wl);
    bool vy0 = (y0 >= 0) & (y0 < Hl), vy1 = (y1 >= 0) & (y1 < Hl);
    int cx0 = min(max(x0, 0), Wl - 1), cx1 = min(max(x1, 0), Wl - 1);
    int cy0 = min(max(y0, 0), Hl - 1), cy1 = min(max(y1, 0), Hl - 1);
    int base = b * LQ_C + c_St[l];
    int r00 = base + cy0 * Wl + cx0;
    int r01 = base + cy0 * Wl + cx1;
    int r10 = base + cy1 * Wl + cx0;
    int r11 = base + cy1 * Wl + cx1;
    float w00 = wA * (1.f - lx) * (1.f - ly) * (float)(vx0 & vy0);
    float w01 = wA * lx * (1.f - ly) * (float)(vx1 & vy0);
    float w10 = wA * (1.f - lx) * ly * (float)(vx0 & vy1);
    float w11 = wA * lx * ly * (float)(vx1 & vy1);

    const __half2* vb2 = (const __half2*)value + h * 16 + (lane & 15);
    const int psel = (lane < 16) ? 0 : 8;
    float2 acc = make_float2(0.f, 0.f);
#pragma unroll
    for (int pp = 0; pp < 8; pp++) {
        int sp = pp + psel;
        int s00 = __shfl_sync(0xffffffffu, r00, sp);
        int s01 = __shfl_sync(0xffffffffu, r01, sp);
        int s10 = __shfl_sync(0xffffffffu, r10, sp);
        int s11 = __shfl_sync(0xffffffffu, r11, sp);
        float u00 = __shfl_sync(0xffffffffu, w00, sp);
        float u01 = __shfl_sync(0xffffffffu, w01, sp);
        float u10 = __shfl_sync(0xffffffffu, w10, sp);
        float u11 = __shfl_sync(0xffffffffu, w11, sp);
        float2 f;
        f = __half22float2(__ldg(vb2 + (size_t)s00 * 128));
        acc.x += u00 * f.x; acc.y += u00 * f.y;
        f = __half22float2(__ldg(vb2 + (size_t)s01 * 128));
        acc.x += u01 * f.x; acc.y += u01 * f.y;
        f = __half22float2(__ldg(vb2 + (size_t)s10 * 128));
        acc.x += u10 * f.x; acc.y += u10 * f.y;
        f = __half22float2(__ldg(vb2 + (size_t)s11 * 128));
        acc.x += u11 * f.x; acc.y += u11 * f.y;
    }
    acc.x += __shfl_xor_sync(0xffffffffu, acc.x, 16);
    acc.y += __shfl_xor_sync(0xffffffffu, acc.y, 16);
    if (lane < 16) {
        ((__half2*)(outh + (size_t)token * 256 + h * 32))[lane] =
            __floats2half2_rn(acc.x, acc.y);
    }
}

// ---------------- text K/V projection (fp16 out) ----------------
__global__ void kv_proj_kernel(const float* __restrict__ text, const float* __restrict__ ipw,
                               const float* __restrict__ ipb, __half* __restrict__ kh,
                               __half* __restrict__ vh) {
    int row = blockIdx.x;
    int c = threadIdx.x;
    const float* t = text + (size_t)row * 256;
    const float* wk = ipw + (size_t)(256 + c) * 256;
    const float* wv = ipw + (size_t)(512 + c) * 256;
    float sk = ipb[256 + c], sv = ipb[512 + c];
    for (int k = 0; k < 256; k++) {
        float tv = t[k];
        sk += tv * wk[k];
        sv += tv * wv[k];
    }
    kh[(size_t)row * 256 + c] = __float2half_rn(sk);
    vh[(size_t)row * 256 + c] = __float2half_rn(sv);
}

// ---------------- text cross-attention (all fp16 I/O) ----------------
__global__ void cross_attn_kernel(const __half* __restrict__ qh, const __half* __restrict__ kh,
                                  const __half* __restrict__ vh, __half* __restrict__ ch) {
    int idx = blockIdx.x * blockDim.x + threadIdx.x;
    if (idx >= NTOK * NH) return;
    int token = idx >> 3, h = idx & 7;
    int b = (token >= LQ_C) ? 1 : 0;
    const __half2* q = (const __half2*)(qh + (size_t)token * 256 + h * 32);
    float2 qv[16];
#pragma unroll
    for (int j = 0; j < 16; j++) qv[j] = __half22float2(q[j]);

    float sc[LT];
    float mx = -1e30f;
    const float scale = 0.17677669529663687f;
#pragma unroll 4
    for (int k = 0; k < LT; k++) {
        const __half2* kp = (const __half2*)(kh + (size_t)(b * LT + k) * 256 + h * 32);
        float s = 0.f;
#pragma unroll
        for (int j = 0; j < 16; j++) {
            float2 kv = __half22float2(kp[j]);
            s += qv[j].x * kv.x + qv[j].y * kv.y;
        }
        s *= scale;
        sc[k] = s;
        mx = fmaxf(mx, s);
    }
    float denom = 0.f;
#pragma unroll
    for (int k = 0; k < LT; k++) { sc[k] = expf(sc[k] - mx); denom += sc[k]; }
    float inv = 1.f / denom;
    float2 o[16];
#pragma unroll
    for (int j = 0; j < 16; j++) o[j] = make_float2(0.f, 0.f);
#pragma unroll 4
    for (int k = 0; k < LT; k++) {
        float pw = sc[k] * inv;
        const __half2* vp = (const __half2*)(vh + (size_t)(b * LT + k) * 256 + h * 32);
#pragma unroll
        for (int j = 0; j < 16; j++) {
            float2 vv = __half22float2(vp[j]);
            o[j].x += pw * vv.x;
            o[j].y += pw * vv.y;
        }
    }
    __half2* cp = (__half2*)(ch + (size_t)token * 256 + h * 32);
#pragma unroll
    for (int j = 0; j < 16; j++) cp[j] = __floats2half2_rn(o[j].x, o[j].y);
}

// ---------------- launch ----------------
extern "C" void kernel_launch(void* const* d_in, const int* in_sizes, int n_in,
                              void* d_out, int out_size) {
    const float* src   = (const float*)d_in[0];
    const float* pos   = (const float*)d_in[1];
    const float* refp  = (const float*)d_in[2];
    const float* text  = (const float*)d_in[5];
    const float* so_w  = (const float*)d_in[7];
    const float* so_b  = (const float*)d_in[8];
    const float* aw_w  = (const float*)d_in[9];
    const float* aw_b  = (const float*)d_in[10];
    const float* vp_w  = (const float*)d_in[11];
    const float* vp_b  = (const float*)d_in[12];
    const float* op_w  = (const float*)d_in[13];
    const float* op_b  = (const float*)d_in[14];
    const float* ln1_g = (const float*)d_in[15];
    const float* ln1_b = (const float*)d_in[16];
    const float* ipw   = (const float*)d_in[17];
    const float* ipb   = (const float*)d_in[18];
    const float* mo_w  = (const float*)d_in[19];
    const float* mo_b  = (const float*)d_in[20];
    const float* ln3_g = (const float*)d_in[21];
    const float* ln3_b = (const float*)d_in[22];
    const float* l1_w  = (const float*)d_in[23];
    const float* l1_b  = (const float*)d_in[24];
    const float* l2_w  = (const float*)d_in[25];
    const float* l2_b  = (const float*)d_in[26];
    const float* ln2_g = (const float*)d_in[27];
    const float* ln2_b = (const float*)d_in[28];

    float* out_x = (float*)d_out;
    float* out_text = out_x + (size_t)NTOK * D_MODEL;

    float *offs, *aw;
    cudaGetSymbolAddress((void**)&offs, g_offs);
    cudaGetSymbolAddress((void**)&aw, g_aw);
    __half *q, *kh, *vh, *val, *A, *B, *hid;
    cudaGetSymbolAddress((void**)&q, g_q);
    cudaGetSymbolAddress((void**)&kh, g_kh);
    cudaGetSymbolAddress((void**)&vh, g_vh);
    cudaGetSymbolAddress((void**)&val, g_val);
    cudaGetSymbolAddress((void**)&A, g_A);
    cudaGetSymbolAddress((void**)&B, g_B);
    cudaGetSymbolAddress((void**)&hid, g_hid);
    __half *vpw, *sow, *aww, *opw, *wqw, *mow, *l1w, *l2w;
    cudaGetSymbolAddress((void**)&vpw, g_vpw);
    cudaGetSymbolAddress((void**)&sow, g_sow);
    cudaGetSymbolAddress((void**)&aww, g_aww);
    cudaGetSymbolAddress((void**)&opw, g_opw);
    cudaGetSymbolAddress((void**)&wqw, g_wqw);
    cudaGetSymbolAddress((void**)&mow, g_mow);
    cudaGetSymbolAddress((void**)&l1w, g_l1w);
    cudaGetSymbolAddress((void**)&l2w, g_l2w);

    cudaFuncSetAttribute((const void*)tc_gemm<0, true>,
                         cudaFuncAttributeMaxDynamicSharedMemorySize, GEMM_SMEM);
    cudaFuncSetAttribute((const void*)tc_gemm<2, true>,
                         cudaFuncAttributeMaxDynamicSharedMemorySize, GEMM_SMEM);
    cudaFuncSetAttribute((const void*)tc_gemm_head,
                         cudaFuncAttributeMaxDynamicSharedMemorySize, GEMM_SMEM);
    cudaFuncSetAttribute((const void*)tc_gemm_ln<true, true>,
                         cudaFuncAttributeMaxDynamicSharedMemorySize, GEMM_LN_SMEM);
    cudaFuncSetAttribute((const void*)tc_gemm_ln<true, false>,
                         cudaFuncAttributeMaxDynamicSharedMemorySize, GEMM_LN_SMEM);
    cudaFuncSetAttribute((const void*)tc_gemm_ln<false, false>,
                         cudaFuncAttributeMaxDynamicSharedMemorySize, GEMM_LN_SMEM);

    const int M = NTOK;
    const int mTiles = cdiv(M, 64);
    dim3 g256(2, mTiles), gHead(5, mTiles), g1024(8, mTiles);
    const int nAct4 = M * D_MODEL / 4;

    // 1: weight conversions (batched)
    WJobs J;
    J.j[0] = {vp_w, vpw, 65536 / 4};
    J.j[1] = {so_w, sow, 65536 / 4};
    J.j[2] = {aw_w, aww, 32768 / 4};
    J.j[3] = {op_w, opw, 65536 / 4};
    J.j[4] = {ipw,  wqw, 65536 / 4};
    J.j[5] = {mo_w, mow, 65536 / 4};
    J.j[6] = {l1_w, l1w, 262144 / 4};
    J.j[7] = {l2_w, l2w, 262144 / 4};
    int totW4 = (65536 * 5 + 32768 + 262144 * 2) / 4;
    wconv_kernel<<<cdiv(totW4, 256), 256>>>(J);
    // 2: activation conversions (src -> A, src+pos -> B)
    actconv_kernel<<<cdiv(nAct4, 256), 256>>>(src, pos, A, B, nAct4);
    // 3: text K/V (fp16)
    kv_proj_kernel<<<B_SZ * LT, 256>>>(text, ipw, ipb, kh, vh);
    // 4: FUSED head GEMMs: val (fp16) + offs + aw (softmax16)
    tc_gemm_head<<<gHead, 256, GEMM_SMEM>>>(A, B, vpw, sow, aww, vp_b, so_b, aw_b,
                                            val, offs, aw, M);
    // 5: deformable sampling -> ms (fp16, into A)
    msdeform_kernel<<<cdiv(M * NH * 32, 256), 256>>>(val, offs, aw, refp, A);
    // 6: fused GEMM+LN1: x = LN(ms@op^T + b + src) -> out_x; (x+pos) -> B
    tc_gemm_ln<true, true><<<mTiles, 256, GEMM_LN_SMEM>>>(A, opw, op_b, src,
                                                          ln1_g, ln1_b, pos, out_x, B,
                                                          M, 256);
    // 7: qh = (x+pos) @ wq^T + bq -> fp16
    tc_gemm<0, true><<<g256, 256, GEMM_SMEM>>>(B, wqw, ipb, (float*)q, M, 256, 256);
    // 8: cross attention -> ctx (fp16, into A)
    cross_attn_kernel<<<cdiv(M * NH, 256), 256>>>(q, kh, vh, A);
    // 9: fused GEMM+LN3: x = LN(ctx@mo^T + b + x) -> out_x; x -> B
    tc_gemm_ln<true, false><<<mTiles, 256, GEMM_LN_SMEM>>>(A, mow, mo_b, out_x,
                                                           ln3_g, ln3_b, nullptr, out_x, B,
                                                           M, 256);
    // 10: hid = relu(x@l1^T + b1) -> fp16
    tc_gemm<2, true><<<g1024, 256, GEMM_SMEM>>>(B, l1w, l1_b, (float*)hid, M, DFF, 256);
    // 11: fused GEMM+LN2: out = LN(hid@l2^T + b2 + x) -> out_x
    tc_gemm_ln<false, false><<<mTiles, 256, GEMM_LN_SMEM>>>(hid, l2w, l2_b, out_x,
                                                            ln2_g, ln2_b, nullptr, out_x,
                                                            nullptr, M, 1024);
    // 12: pass-through text_memory
    cudaMemcpyAsync(out_text, text, (size_t)B_SZ * LT * D_MODEL * sizeof(float),
                    cudaMemcpyDeviceToDevice, 0);
}

// round 17
// speedup vs baseline: 1.0975x; 1.0975x over previous
#include <cuda_runtime.h>
#include <cuda_fp16.h>
#include <cstdint>
#include <math.h>

// ---------------- problem constants ----------------
#define D_MODEL 256
#define NH 8
#define HD 32
#define NL 4
#define NP 4
#define DFF 1024
#define B_SZ 2
#define LT 20
#define LQ_C 20197
#define NTOK (B_SZ * LQ_C)   // 40394

__device__ __constant__ int c_H[NL]  = {100, 50, 25, 13};
__device__ __constant__ int c_W[NL]  = {152, 76, 38, 19};
__device__ __constant__ int c_St[NL] = {0, 15200, 19000, 19950};

// ---------------- scratch (static device globals; no allocation) ----------------
__device__ float g_offs[NTOK * D_MODEL];
__device__ float g_aw[NTOK * 128];
__device__ __half g_q[NTOK * D_MODEL];
__device__ __half g_kh[B_SZ * LT * D_MODEL];
__device__ __half g_vh[B_SZ * LT * D_MODEL];
__device__ __half g_val[NTOK * D_MODEL];
__device__ __half g_A[NTOK * D_MODEL];
__device__ __half g_B[NTOK * D_MODEL];
__device__ __half g_hid[NTOK * DFF];
__device__ __half g_vpw[65536];
__device__ __half g_sow[65536];
__device__ __half g_aww[32768];
__device__ __half g_opw[65536];
__device__ __half g_wqw[65536];
__device__ __half g_mow[65536];
__device__ __half g_l1w[262144];
__device__ __half g_l2w[262144];

static inline int cdiv(int a, int b) { return (a + b - 1) / b; }

__device__ __forceinline__ uint32_t smem_u32(const void* p) {
    uint32_t a;
    asm("{ .reg .u64 t; cvta.to.shared.u64 t, %1; cvt.u32.u64 %0, t; }" : "=r"(a) : "l"(p));
    return a;
}
__device__ __forceinline__ void ldm_x4(uint32_t addr, uint32_t& r0, uint32_t& r1,
                                       uint32_t& r2, uint32_t& r3) {
    asm volatile("ldmatrix.sync.aligned.m8n8.x4.shared.b16 {%0,%1,%2,%3}, [%4];"
                 : "=r"(r0), "=r"(r1), "=r"(r2), "=r"(r3) : "r"(addr));
}
__device__ __forceinline__ void mma_f16(float* c, const uint32_t* a, const uint32_t* b) {
    asm volatile(
        "mma.sync.aligned.m16n8k16.row.col.f32.f16.f16.f32 "
        "{%0,%1,%2,%3}, {%4,%5,%6,%7}, {%8,%9}, {%0,%1,%2,%3};"
        : "+f"(c[0]), "+f"(c[1]), "+f"(c[2]), "+f"(c[3])
        : "r"(a[0]), "r"(a[1]), "r"(a[2]), "r"(a[3]), "r"(b[0]), "r"(b[1]));
}
__device__ __forceinline__ uint2 f4_to_h4(float4 v) {
    union { __half2 h2[2]; uint2 u; } U;
    U.h2[0] = __floats2half2_rn(v.x, v.y);
    U.h2[1] = __floats2half2_rn(v.z, v.w);
    return U.u;
}
__device__ __forceinline__ void cpa16(uint32_t dst, const void* src) {
    asm volatile("cp.async.cg.shared.global [%0], [%1], 16;" :: "r"(dst), "l"(src));
}
__device__ __forceinline__ void cpa16z(uint32_t dst, const void* src, bool v) {
    int sz = v ? 16 : 0;
    asm volatile("cp.async.cg.shared.global [%0], [%1], 16, %2;"
                 :: "r"(dst), "l"(src), "r"(sz));
}

#define KC 64
#define A_TILE_B 8192
#define B_TILE_B 16384
#define STAGE_B (A_TILE_B + B_TILE_B)   // 24 KB
#define NSTAGE 3
#define GEMM_SMEM (NSTAGE * STAGE_B)    // 72 KB -> 3 CTAs/SM

// =====================================================================
// GEMM mainloop core (CTA 64x128, 256 thr, warp 32x32, KC=64, 3 stages,
// 1 sync/chunk). Produces acc[2][4][4] for this CTA's 64x128 tile.
// =====================================================================
struct GemmCore {
    float acc[2][4][4];

    __device__ __forceinline__ void run(uint32_t sbase, const __half* Aop, const __half* bW,
                                        int rowBase, int M, int K,
                                        int tid, int wid, int lane) {
        const int warpM = wid >> 2;
        const int warpN = wid & 3;
#pragma unroll
        for (int mi = 0; mi < 2; mi++)
#pragma unroll
            for (int ni = 0; ni < 4; ni++)
#pragma unroll
                for (int j = 0; j < 4; j++) acc[mi][ni][j] = 0.f;

        const uint32_t swX = (uint32_t)((lane & 7) << 4);
        const int aKB0 = (lane >> 4) * 16;
        uint32_t aRowOff[2];
#pragma unroll
        for (int mi = 0; mi < 2; mi++)
            aRowOff[mi] = (uint32_t)((warpM * 32 + mi * 16 + (lane & 15)) * 128);
        const int grp = lane >> 3;
        const int bKB0 = (grp & 1) * 16;
        uint32_t bRowOff[2];
#pragma unroll
        for (int np = 0; np < 2; np++)
            bRowOff[np] = (uint32_t)((warpN * 32 + np * 16 + ((grp >> 1) << 3) + (lane & 7)) * 128);

        const int nChunks = K / KC;
        auto copy_chunk = [&](int kt, uint32_t stg) {
            const int k0 = kt * KC;
#pragma unroll
            for (int i = 0; i < 4; i++) {
                int idx = tid + i * 256;
                int r = idx >> 3, c = idx & 7;
                uint32_t off = (uint32_t)(r * 128 + ((c * 16) ^ ((r & 7) << 4)));
                cpa16(stg + A_TILE_B + off, bW + (size_t)r * K + k0 + c * 8);
            }
#pragma unroll
            for (int i = 0; i < 2; i++) {
                int idx = tid + i * 256;
                int r = idx >> 3, c = idx & 7;
                uint32_t off = (uint32_t)(r * 128 + ((c * 16) ^ ((r & 7) << 4)));
                int gr = rowBase + r;
                bool v = gr < M;
                int crr = v ? gr : (M - 1);
                cpa16z(stg + off, Aop + (size_t)crr * K + k0 + c * 8, v);
            }
        };

        copy_chunk(0, sbase);
        asm volatile("cp.async.commit_group;");
        if (nChunks > 1) {
            copy_chunk(1, sbase + STAGE_B);
            asm volatile("cp.async.commit_group;");
        }
        int stgIdx = 0;
        for (int kt = 0; kt < nChunks; kt++) {
            if (kt + 1 < nChunks) asm volatile("cp.async.wait_group 1;");
            else asm volatile("cp.async.wait_group 0;");
            __syncthreads();
            if (kt + 2 < nChunks) {
                int ws = stgIdx + 2;
                if (ws >= NSTAGE) ws -= NSTAGE;
                copy_chunk(kt + 2, sbase + (uint32_t)(ws * STAGE_B));
                asm volatile("cp.async.commit_group;");
            }
            const uint32_t AS = sbase + (uint32_t)(stgIdx * STAGE_B);
            const uint32_t BS = AS + A_TILE_B;
#pragma unroll
            for (int kst = 0; kst < 4; kst++) {
                uint32_t a[2][4];
#pragma unroll
                for (int mi = 0; mi < 2; mi++) {
                    uint32_t kb = (uint32_t)(aKB0 + kst * 32);
                    ldm_x4(AS + aRowOff[mi] + (kb ^ swX),
                           a[mi][0], a[mi][1], a[mi][2], a[mi][3]);
                }
                uint32_t b[4][2];
#pragma unroll
                for (int np = 0; np < 2; np++) {
                    uint32_t kb = (uint32_t)(bKB0 + kst * 32);
                    uint32_t r0, r1, r2, r3;
                    ldm_x4(BS + bRowOff[np] + (kb ^ swX), r0, r1, r2, r3);
                    b[np * 2][0] = r0; b[np * 2][1] = r1;
                    b[np * 2 + 1][0] = r2; b[np * 2 + 1][1] = r3;
                }
#pragma unroll
                for (int mi = 0; mi < 2; mi++)
#pragma unroll
                    for (int ni = 0; ni < 4; ni++) mma_f16(acc[mi][ni], a[mi], b[ni]);
            }
            stgIdx++;
            if (stgIdx == NSTAGE) stgIdx = 0;
        }
    }
};

// =====================================================================
// tc_gemm: MODE 0: +bias  2: +bias,relu.  OH: half output.
// =====================================================================
template <int MODE, bool OH>
__global__ void __launch_bounds__(256, 3)
tc_gemm(const __half* __restrict__ A, const __half* __restrict__ W,
        const float* __restrict__ bias, float* __restrict__ C,
        int M, int N, int K) {
    extern __shared__ char smem[];
    const uint32_t sbase = smem_u32(smem);
    const int tid = threadIdx.x;
    const int wid = tid >> 5;
    const int lane = tid & 31;
    const int rowBase = blockIdx.y * 64;
    const int colBase = blockIdx.x * 128;
    const int warpM = wid >> 2;
    const int warpN = wid & 3;

    GemmCore gc;
    gc.run(sbase, A, W + (size_t)colBase * K, rowBase, M, K, tid, wid, lane);

    const int qrow = lane >> 2;
    const int qcol = (lane & 3) * 2;
#pragma unroll
    for (int ni = 0; ni < 4; ni++) {
        int col = colBase + warpN * 32 + ni * 8 + qcol;
        float b0 = __ldg(bias + col), b1 = __ldg(bias + col + 1);
#pragma unroll
        for (int mi = 0; mi < 2; mi++) {
            gc.acc[mi][ni][0] += b0; gc.acc[mi][ni][1] += b1;
            gc.acc[mi][ni][2] += b0; gc.acc[mi][ni][3] += b1;
        }
    }
#pragma unroll
    for (int mi = 0; mi < 2; mi++)
#pragma unroll
        for (int rh = 0; rh < 2; rh++) {
            int row = rowBase + warpM * 32 + mi * 16 + qrow + rh * 8;
            if (row >= M) continue;
#pragma unroll
            for (int ni = 0; ni < 4; ni++) {
                int col = colBase + warpN * 32 + ni * 8 + qcol;
                float v0 = gc.acc[mi][ni][rh * 2], v1 = gc.acc[mi][ni][rh * 2 + 1];
                if (MODE == 2) { v0 = fmaxf(v0, 0.f); v1 = fmaxf(v1, 0.f); }
                if (OH)
                    *(__half2*)((__half*)C + (size_t)row * N + col) = __floats2half2_rn(v0, v1);
                else
                    *(float2*)(C + (size_t)row * N + col) = make_float2(v0, v1);
            }
        }
}

// =====================================================================
// tc_gemm_head: fused head GEMMs. grid (5, mTiles).
//   x 0,1: val = src @ vp^T + b      (half out)
//   x 2,3: offs = q  @ so^T + b      (f32 out)
//   x 4:   aw = softmax16(q @ aw^T + b)
// =====================================================================
__global__ void __launch_bounds__(256, 3)
tc_gemm_head(const __half* __restrict__ Asrc, const __half* __restrict__ Aq,
             const __half* __restrict__ Wvp, const __half* __restrict__ Wso,
             const __half* __restrict__ Waw,
             const float* __restrict__ vp_b, const float* __restrict__ so_b,
             const float* __restrict__ aw_b,
             __half* __restrict__ val, float* __restrict__ offs, float* __restrict__ aw,
             int M) {
    extern __shared__ char smem[];
    const uint32_t sbase = smem_u32(smem);
    const int tid = threadIdx.x;
    const int wid = tid >> 5;
    const int lane = tid & 31;
    const int rowBase = blockIdx.y * 64;
    const int bx = blockIdx.x;
    const int warpM = wid >> 2;
    const int warpN = wid & 3;
    const int K = 256;

    int mode, colBase;
    const __half* Aop;
    const __half* Wop;
    const float* bp;
    if (bx < 2) { mode = 0; colBase = bx * 128; Aop = Asrc; Wop = Wvp; bp = vp_b; }
    else if (bx < 4) { mode = 1; colBase = (bx - 2) * 128; Aop = Aq; Wop = Wso; bp = so_b; }
    else { mode = 2; colBase = 0; Aop = Aq; Wop = Waw; bp = aw_b; }

    GemmCore gc;
    gc.run(sbase, Aop, Wop + (size_t)colBase * K, rowBase, M, K, tid, wid, lane);

    const int qrow = lane >> 2;
    const int qcol = (lane & 3) * 2;
#pragma unroll
    for (int ni = 0; ni < 4; ni++) {
        int col = colBase + warpN * 32 + ni * 8 + qcol;
        float b0 = __ldg(bp + col), b1 = __ldg(bp + col + 1);
#pragma unroll
        for (int mi = 0; mi < 2; mi++) {
            gc.acc[mi][ni][0] += b0; gc.acc[mi][ni][1] += b1;
            gc.acc[mi][ni][2] += b0; gc.acc[mi][ni][3] += b1;
        }
    }
    if (mode == 2) {
#pragma unroll
        for (int mi = 0; mi < 2; mi++)
#pragma unroll
            for (int g = 0; g < 2; g++)
#pragma unroll
                for (int rh = 0; rh < 2; rh++) {
                    float v0 = gc.acc[mi][2 * g][rh * 2], v1 = gc.acc[mi][2 * g][rh * 2 + 1];
                    float v2 = gc.acc[mi][2 * g + 1][rh * 2], v3 = gc.acc[mi][2 * g + 1][rh * 2 + 1];
                    float mx = fmaxf(fmaxf(v0, v1), fmaxf(v2, v3));
                    mx = fmaxf(mx, __shfl_xor_sync(0xffffffffu, mx, 1));
                    mx = fmaxf(mx, __shfl_xor_sync(0xffffffffu, mx, 2));
                    v0 = expf(v0 - mx); v1 = expf(v1 - mx);
                    v2 = expf(v2 - mx); v3 = expf(v3 - mx);
                    float s = v0 + v1 + v2 + v3;
                    s += __shfl_xor_sync(0xffffffffu, s, 1);
                    s += __shfl_xor_sync(0xffffffffu, s, 2);
                    float inv = 1.f / s;
                    gc.acc[mi][2 * g][rh * 2] = v0 * inv;
                    gc.acc[mi][2 * g][rh * 2 + 1] = v1 * inv;
                    gc.acc[mi][2 * g + 1][rh * 2] = v2 * inv;
                    gc.acc[mi][2 * g + 1][rh * 2 + 1] = v3 * inv;
                }
    }
#pragma unroll
    for (int mi = 0; mi < 2; mi++)
#pragma unroll
        for (int rh = 0; rh < 2; rh++) {
            int row = rowBase + warpM * 32 + mi * 16 + qrow + rh * 8;
            if (row >= M) continue;
#pragma unroll
            for (int ni = 0; ni < 4; ni++) {
                int cl_ = warpN * 32 + ni * 8 + qcol;
                float v0 = gc.acc[mi][ni][rh * 2], v1 = gc.acc[mi][ni][rh * 2 + 1];
                if (mode == 0) {
                    *(__half2*)(val + (size_t)row * 256 + colBase + cl_) =
                        __floats2half2_rn(v0, v1);
                } else if (mode == 1) {
                    *(float2*)(offs + (size_t)row * 256 + colBase + cl_) = make_float2(v0, v1);
                } else {
                    *(float2*)(aw + (size_t)row * 128 + cl_) = make_float2(v0, v1);
                }
            }
        }
}

// =====================================================================
// tc_gemm_ln: fp16 GEMM + residual + fused LayerNorm. CTA 64x256 (full rows),
//   8 warps (warp tile 32x64), KC=64, 2 stages (40 KB each), 2 CTAs/SM.
// =====================================================================
#define LA_TILE_B 8192
#define LB_TILE_B 32768
#define LSTAGE_B (LA_TILE_B + LB_TILE_B)
#define GEMM_LN_SMEM (2 * LSTAGE_B)     // 80 KB

template <bool WANTH, bool HASP>
__global__ void __launch_bounds__(256, 2)
tc_gemm_ln(const __half* __restrict__ A, const __half* __restrict__ W,
           const float* __restrict__ bias, const float* __restrict__ R,
           const float* __restrict__ lng, const float* __restrict__ lnb,
           const float* __restrict__ P, float* __restrict__ Cout,
           __half* __restrict__ Sh, int M, int K) {
    extern __shared__ char smem[];
    const uint32_t sbase = smem_u32(smem);
    const int tid = threadIdx.x;
    const int wid = tid >> 5;
    const int lane = tid & 31;
    const int rowBase = blockIdx.x * 64;
    const int warpM = wid >> 2;
    const int warpN = wid & 3;

    float acc[2][8][4];
#pragma unroll
    for (int mi = 0; mi < 2; mi++)
#pragma unroll
        for (int ni = 0; ni < 8; ni++)
#pragma unroll
            for (int j = 0; j < 4; j++) acc[mi][ni][j] = 0.f;

    const uint32_t swX = (uint32_t)((lane & 7) << 4);
    const int aKB0 = (lane >> 4) * 16;
    uint32_t aRowOff[2];
#pragma unroll
    for (int mi = 0; mi < 2; mi++)
        aRowOff[mi] = (uint32_t)((warpM * 32 + mi * 16 + (lane & 15)) * 128);
    const int grp = lane >> 3;
    const int bKB0 = (grp & 1) * 16;
    uint32_t bRowOff[4];
#pragma unroll
    for (int np = 0; np < 4; np++)
        bRowOff[np] = (uint32_t)((warpN * 64 + np * 16 + ((grp >> 1) << 3) + (lane & 7)) * 128);

    const int nChunks = K / KC;

    auto copy_chunk = [&](int kt, uint32_t stg) {
        const int k0 = kt * KC;
#pragma unroll
        for (int i = 0; i < 8; i++) {
            int idx = tid + i * 256;
            int r = idx >> 3, c = idx & 7;
            uint32_t off = (uint32_t)(r * 128 + ((c * 16) ^ ((r & 7) << 4)));
            cpa16(stg + LA_TILE_B + off, W + (size_t)r * K + k0 + c * 8);
        }
#pragma unroll
        for (int i = 0; i < 2; i++) {
            int idx = tid + i * 256;
            int r = idx >> 3, c = idx & 7;
            uint32_t off = (uint32_t)(r * 128 + ((c * 16) ^ ((r & 7) << 4)));
            int gr = rowBase + r;
            bool v = gr < M;
            int crr = v ? gr : (M - 1);
            cpa16z(stg + off, A + (size_t)crr * K + k0 + c * 8, v);
        }
    };

    copy_chunk(0, sbase);
    asm volatile("cp.async.commit_group;");
    for (int kt = 0; kt < nChunks; kt++) {
        if (kt + 1 < nChunks) {
            copy_chunk(kt + 1, sbase + (uint32_t)(((kt + 1) & 1) * LSTAGE_B));
            asm volatile("cp.async.commit_group;");
            asm volatile("cp.async.wait_group 1;");
        } else {
            asm volatile("cp.async.wait_group 0;");
        }
        __syncthreads();
        const uint32_t AS = sbase + (uint32_t)((kt & 1) * LSTAGE_B);
        const uint32_t BS = AS + LA_TILE_B;
#pragma unroll
        for (int kst = 0; kst < 4; kst++) {
            uint32_t a[2][4];
#pragma unroll
            for (int mi = 0; mi < 2; mi++) {
                uint32_t kb = (uint32_t)(aKB0 + kst * 32);
                ldm_x4(AS + aRowOff[mi] + (kb ^ swX), a[mi][0], a[mi][1], a[mi][2], a[mi][3]);
            }
#pragma unroll
            for (int np = 0; np < 4; np++) {
                uint32_t kb = (uint32_t)(bKB0 + kst * 32);
                uint32_t r0, r1, r2, r3;
                ldm_x4(BS + bRowOff[np] + (kb ^ swX), r0, r1, r2, r3);
                uint32_t b0[2] = {r0, r1}, b1[2] = {r2, r3};
#pragma unroll
                for (int mi = 0; mi < 2; mi++) {
                    mma_f16(acc[mi][2 * np], a[mi], b0);
                    mma_f16(acc[mi][2 * np + 1], a[mi], b1);
                }
            }
        }
        if (kt + 1 < nChunks) __syncthreads();
    }

    // ---- fused epilogue: bias + residual + LayerNorm ----
    __syncthreads();
    float* red = (float*)smem;
    const int qrow = lane >> 2;
    const int qcol = (lane & 3) * 2;

#pragma unroll
    for (int mi = 0; mi < 2; mi++)
#pragma unroll
        for (int rh = 0; rh < 2; rh++) {
            int rloc = warpM * 32 + mi * 16 + rh * 8 + qrow;
            int row = rowBase + rloc;
            bool ok = row < M;
            float s = 0.f, qsum = 0.f;
#pragma unroll
            for (int ni = 0; ni < 8; ni++) {
                int col = warpN * 64 + ni * 8 + qcol;
                float b0 = __ldg(bias + col), b1 = __ldg(bias + col + 1);
                float v0 = acc[mi][ni][rh * 2] + b0;
                float v1 = acc[mi][ni][rh * 2 + 1] + b1;
                if (ok) {
                    const float2 rr = *(const float2*)(R + (size_t)row * 256 + col);
                    v0 += rr.x; v1 += rr.y;
                }
                acc[mi][ni][rh * 2] = v0;
                acc[mi][ni][rh * 2 + 1] = v1;
                s += v0 + v1;
                qsum += v0 * v0 + v1 * v1;
            }
            s += __shfl_xor_sync(0xffffffffu, s, 1);
            s += __shfl_xor_sync(0xffffffffu, s, 2);
            qsum += __shfl_xor_sync(0xffffffffu, qsum, 1);
            qsum += __shfl_xor_sync(0xffffffffu, qsum, 2);
            if ((lane & 3) == 0) {
                red[(rloc << 3) + (warpN << 1)] = s;
                red[(rloc << 3) + (warpN << 1) + 1] = qsum;
            }
        }
    __syncthreads();
#pragma unroll
    for (int mi = 0; mi < 2; mi++)
#pragma unroll
        for (int rh = 0; rh < 2; rh++) {
            int rloc = warpM * 32 + mi * 16 + rh * 8 + qrow;
            int row = rowBase + rloc;
            if (row >= M) continue;
            float s = red[(rloc << 3)] + red[(rloc << 3) + 2] +
                      red[(rloc << 3) + 4] + red[(rloc << 3) + 6];
            float qsum = red[(rloc << 3) + 1] + red[(rloc << 3) + 3] +
                         red[(rloc << 3) + 5] + red[(rloc << 3) + 7];
            float mean = s * (1.f / 256.f);
            float var = qsum * (1.f / 256.f) - mean * mean;
            float rstd = rsqrtf(var + 1e-5f);
#pragma unroll
            for (int ni = 0; ni < 8; ni++) {
                int col = warpN * 64 + ni * 8 + qcol;
                float g0 = __ldg(lng + col), g1 = __ldg(lng + col + 1);
                float c0 = __ldg(lnb + col), c1 = __ldg(lnb + col + 1);
                float y0 = (acc[mi][ni][rh * 2] - mean) * rstd * g0 + c0;
                float y1 = (acc[mi][ni][rh * 2 + 1] - mean) * rstd * g1 + c1;
                *(float2*)(Cout + (size_t)row * 256 + col) = make_float2(y0, y1);
                if (WANTH) {
                    float t0 = y0, t1 = y1;
                    if (HASP) {
                        const float2 pp = *(const float2*)(P + (size_t)row * 256 + col);
                        t0 += pp.x; t1 += pp.y;
                    }
                    *(__half2*)(Sh + (size_t)row * 256 + col) = __floats2half2_rn(t0, t1);
                }
            }
        }
}

// ---------------- batched weight conversion (fp32 -> fp16) ----------------
struct WJob { const float* s; __half* h; int n4; };
struct WJobs { WJob j[8]; };
__global__ void wconv_kernel(WJobs J) {
    int i = blockIdx.x * blockDim.x + threadIdx.x;
#pragma unroll
    for (int k = 0; k < 8; k++) {
        int n = J.j[k].n4;
        if (i < n) {
            ((uint2*)J.j[k].h)[i] = f4_to_h4(((const float4*)J.j[k].s)[i]);
            return;
        }
        i -= n;
    }
}
__global__ void actconv_kernel(const float* __restrict__ src, const float* __restrict__ pos,
                               __half* __restrict__ A, __half* __restrict__ B, int n4) {
    int i = blockIdx.x * blockDim.x + threadIdx.x;
    if (i >= n4) return;
    float4 s = ((const float4*)src)[i];
    float4 p = ((const float4*)pos)[i];
    ((uint2*)A)[i] = f4_to_h4(s);
    s.x += p.x; s.y += p.y; s.z += p.z; s.w += p.w;
    ((uint2*)B)[i] = f4_to_h4(s);
}

// ---------------- multi-scale deformable sampling ----------------
__global__ void msdeform_kernel(const __half* __restrict__ value, const float* __restrict__ offs,
                                const float* __restrict__ aw, const float* __restrict__ ref,
                                __half* __restrict__ outh) {
    int gw = (blockIdx.x * blockDim.x + threadIdx.x) >> 5;
    int lane = threadIdx.x & 31;
    if (gw >= NTOK * NH) return;
    int token = gw >> 3, h = gw & 7;
    int b = (token >= LQ_C) ? 1 : 0;

    int p = lane & 15;
    int l = p >> 2;
    int Wl = c_W[l], Hl = c_H[l];
    float Wf = (float)Wl, Hf = (float)Hl;
    float rx = __ldg(ref + (size_t)token * 8 + l * 2);
    float ry = __ldg(ref + (size_t)token * 8 + l * 2 + 1);
    float ox = __ldg(offs + (size_t)token * 256 + h * 32 + p * 2);
    float oy = __ldg(offs + (size_t)token * 256 + h * 32 + p * 2 + 1);
    float wA = __ldg(aw + (size_t)token * 128 + h * 16 + p);

    float X = (rx + ox / Wf) * Wf - 0.5f;
    float Y = (ry + oy / Hf) * Hf - 0.5f;
    float x0f = floorf(X), y0f = floorf(Y);
    float lx = X - x0f, ly = Y - y0f;
    int x0 = (int)x0f, y0 = (int)y0f;
    int x1 = x0 + 1, y1 = y0 + 1;
    bool vx0 = (x0 >= 0) & (x0 < Wl), vx1 = (x1 >= 0) & (x1 < Wl);
    bool vy0 = (y0 >= 0) & (y0 < Hl), vy1 = (y1 >= 0) & (y1 < Hl);
    int cx0 = min(max(x0, 0), Wl - 1), cx1 = min(max(x1, 0), Wl - 1);
    int cy0 = min(max(y0, 0), Hl - 1), cy1 = min(max(y1, 0), Hl - 1);
    int base = b * LQ_C + c_St[l];
    int r00 = base + cy0 * Wl + cx0;
    int r01 = base + cy0 * Wl + cx1;
    int r10 = base + cy1 * Wl + cx0;
    int r11 = base + cy1 * Wl + cx1;
    float w00 = wA * (1.f - lx) * (1.f - ly) * (float)(vx0 & vy0);
    float w01 = wA * lx * (1.f - ly) * (float)(vx1 & vy0);
    float w10 = wA * (1.f - lx) * ly * (float)(vx0 & vy1);
    float w11 = wA * lx * ly * (float)(vx1 & vy1);

    const __half2* vb2 = (const __half2*)value + h * 16 + (lane & 15);
    const int psel = (lane < 16) ? 0 : 8;
    float2 acc = make_float2(0.f, 0.f);
#pragma unroll
    for (int pp = 0; pp < 8; pp++) {
        int sp = pp + psel;
        int s00 = __shfl_sync(0xffffffffu, r00, sp);
        int s01 = __shfl_sync(0xffffffffu, r01, sp);
        int s10 = __shfl_sync(0xffffffffu, r10, sp);
        int s11 = __shfl_sync(0xffffffffu, r11, sp);
        float u00 = __shfl_sync(0xffffffffu, w00, sp);
        float u01 = __shfl_sync(0xffffffffu, w01, sp);
        float u10 = __shfl_sync(0xffffffffu, w10, sp);
        float u11 = __shfl_sync(0xffffffffu, w11, sp);
        float2 f;
        f = __half22float2(__ldg(vb2 + (size_t)s00 * 128));
        acc.x += u00 * f.x; acc.y += u00 * f.y;
        f = __half22float2(__ldg(vb2 + (size_t)s01 * 128));
        acc.x += u01 * f.x; acc.y += u01 * f.y;
        f = __half22float2(__ldg(vb2 + (size_t)s10 * 128));
        acc.x += u10 * f.x; acc.y += u10 * f.y;
        f = __half22float2(__ldg(vb2 + (size_t)s11 * 128));
        acc.x += u11 * f.x; acc.y += u11 * f.y;
    }
    acc.x += __shfl_xor_sync(0xffffffffu, acc.x, 16);
    acc.y += __shfl_xor_sync(0xffffffffu, acc.y, 16);
    if (lane < 16) {
        ((__half2*)(outh + (size_t)token * 256 + h * 32))[lane] =
            __floats2half2_rn(acc.x, acc.y);
    }
}

// ---------------- text K/V projection (fp16 out) ----------------
__global__ void kv_proj_kernel(const float* __restrict__ text, const float* __restrict__ ipw,
                               const float* __restrict__ ipb, __half* __restrict__ kh,
                               __half* __restrict__ vh) {
    int row = blockIdx.x;
    int c = threadIdx.x;
    const float* t = text + (size_t)row * 256;
    const float* wk = ipw + (size_t)(256 + c) * 256;
    const float* wv = ipw + (size_t)(512 + c) * 256;
    float sk = ipb[256 + c], sv = ipb[512 + c];
    for (int k = 0; k < 256; k++) {
        float tv = t[k];
        sk += tv * wk[k];
        sv += tv * wv[k];
    }
    kh[(size_t)row * 256 + c] = __float2half_rn(sk);
    vh[(size_t)row * 256 + c] = __float2half_rn(sv);
}

// ---------------- text cross-attention: k/v cached in smem ----------------
// All 40 (b,k) rows of kh/vh (both batches) staged per block. Padded per-head
// slab (stride 1284 halfs -> bank distance 2 per h) keeps reads conflict-free
// (broadcast within same-h lanes, 8 distinct banks across heads).
#define CA_STRIDE 1284   // 40*32 + 4 pad halfs; *2B = 2568 B (8B aligned)
__global__ void __launch_bounds__(256)
cross_attn_kernel(const __half* __restrict__ qh, const __half* __restrict__ kh,
                  const __half* __restrict__ vh, __half* __restrict__ ch) {
    __shared__ __half sk[8 * CA_STRIDE];
    __shared__ __half sv[8 * CA_STRIDE];
    const int tid = threadIdx.x;
    // cooperative stage: 40 rows x 64 uint2-chunks (4 halfs each) = 2560 chunks
    for (int i = tid; i < 2560; i += 256) {
        int row = i >> 6;          // (b*LT + k), 0..39
        int c4 = i & 63;           // 4-half chunk within 256-col row
        int h = c4 >> 3;           // head (32 halfs = 8 chunks per head)
        int j4 = c4 & 7;
        *(uint2*)(sk + h * CA_STRIDE + row * 32 + j4 * 4) =
            *(const uint2*)(kh + (size_t)row * 256 + c4 * 4);
        *(uint2*)(sv + h * CA_STRIDE + row * 32 + j4 * 4) =
            *(const uint2*)(vh + (size_t)row * 256 + c4 * 4);
    }
    __syncthreads();

    int idx = blockIdx.x * 256 + tid;
    if (idx >= NTOK * NH) return;
    int token = idx >> 3, h = idx & 7;
    int b = (token >= LQ_C) ? 1 : 0;
    const __half2* q = (const __half2*)(qh + (size_t)token * 256 + h * 32);
    float2 qv[16];
#pragma unroll
    for (int j = 0; j < 16; j++) qv[j] = __half22float2(q[j]);

    const __half2* kp0 = (const __half2*)(sk + h * CA_STRIDE) + b * LT * 16;
    const __half2* vp0 = (const __half2*)(sv + h * CA_STRIDE) + b * LT * 16;

    float sc[LT];
    float mx = -1e30f;
    const float scale = 0.17677669529663687f;
#pragma unroll 4
    for (int k = 0; k < LT; k++) {
        const __half2* kp = kp0 + k * 16;
        float s = 0.f;
#pragma unroll
        for (int j = 0; j < 16; j++) {
            float2 kv = __half22float2(kp[j]);
            s += qv[j].x * kv.x + qv[j].y * kv.y;
        }
        s *= scale;
        sc[k] = s;
        mx = fmaxf(mx, s);
    }
    float denom = 0.f;
#pragma unroll
    for (int k = 0; k < LT; k++) { sc[k] = expf(sc[k] - mx); denom += sc[k]; }
    float inv = 1.f / denom;
    float2 o[16];
#pragma unroll
    for (int j = 0; j < 16; j++) o[j] = make_float2(0.f, 0.f);
#pragma unroll 4
    for (int k = 0; k < LT; k++) {
        float pw = sc[k] * inv;
        const __half2* vp = vp0 + k * 16;
#pragma unroll
        for (int j = 0; j < 16; j++) {
            float2 vv = __half22float2(vp[j]);
            o[j].x += pw * vv.x;
            o[j].y += pw * vv.y;
        }
    }
    __half2* cp = (__half2*)(ch + (size_t)token * 256 + h * 32);
#pragma unroll
    for (int j = 0; j < 16; j++) cp[j] = __floats2half2_rn(o[j].x, o[j].y);
}

// ---------------- launch ----------------
extern "C" void kernel_launch(void* const* d_in, const int* in_sizes, int n_in,
                              void* d_out, int out_size) {
    const float* src   = (const float*)d_in[0];
    const float* pos   = (const float*)d_in[1];
    const float* refp  = (const float*)d_in[2];
    const float* text  = (const float*)d_in[5];
    const float* so_w  = (const float*)d_in[7];
    const float* so_b  = (const float*)d_in[8];
    const float* aw_w  = (const float*)d_in[9];
    const float* aw_b  = (const float*)d_in[10];
    const float* vp_w  = (const float*)d_in[11];
    const float* vp_b  = (const float*)d_in[12];
    const float* op_w  = (const float*)d_in[13];
    const float* op_b  = (const float*)d_in[14];
    const float* ln1_g = (const float*)d_in[15];
    const float* ln1_b = (const float*)d_in[16];
    const float* ipw   = (const float*)d_in[17];
    const float* ipb   = (const float*)d_in[18];
    const float* mo_w  = (const float*)d_in[19];
    const float* mo_b  = (const float*)d_in[20];
    const float* ln3_g = (const float*)d_in[21];
    const float* ln3_b = (const float*)d_in[22];
    const float* l1_w  = (const float*)d_in[23];
    const float* l1_b  = (const float*)d_in[24];
    const float* l2_w  = (const float*)d_in[25];
    const float* l2_b  = (const float*)d_in[26];
    const float* ln2_g = (const float*)d_in[27];
    const float* ln2_b = (const float*)d_in[28];

    float* out_x = (float*)d_out;
    float* out_text = out_x + (size_t)NTOK * D_MODEL;

    float *offs, *aw;
    cudaGetSymbolAddress((void**)&offs, g_offs);
    cudaGetSymbolAddress((void**)&aw, g_aw);
    __half *q, *kh, *vh, *val, *A, *B, *hid;
    cudaGetSymbolAddress((void**)&q, g_q);
    cudaGetSymbolAddress((void**)&kh, g_kh);
    cudaGetSymbolAddress((void**)&vh, g_vh);
    cudaGetSymbolAddress((void**)&val, g_val);
    cudaGetSymbolAddress((void**)&A, g_A);
    cudaGetSymbolAddress((void**)&B, g_B);
    cudaGetSymbolAddress((void**)&hid, g_hid);
    __half *vpw, *sow, *aww, *opw, *wqw, *mow, *l1w, *l2w;
    cudaGetSymbolAddress((void**)&vpw, g_vpw);
    cudaGetSymbolAddress((void**)&sow, g_sow);
    cudaGetSymbolAddress((void**)&aww, g_aww);
    cudaGetSymbolAddress((void**)&opw, g_opw);
    cudaGetSymbolAddress((void**)&wqw, g_wqw);
    cudaGetSymbolAddress((void**)&mow, g_mow);
    cudaGetSymbolAddress((void**)&l1w, g_l1w);
    cudaGetSymbolAddress((void**)&l2w, g_l2w);

    cudaFuncSetAttribute((const void*)tc_gemm<0, true>,
                         cudaFuncAttributeMaxDynamicSharedMemorySize, GEMM_SMEM);
    cudaFuncSetAttribute((const void*)tc_gemm<2, true>,
                         cudaFuncAttributeMaxDynamicSharedMemorySize, GEMM_SMEM);
    cudaFuncSetAttribute((const void*)tc_gemm_head,
                         cudaFuncAttributeMaxDynamicSharedMemorySize, GEMM_SMEM);
    cudaFuncSetAttribute((const void*)tc_gemm_ln<true, true>,
                         cudaFuncAttributeMaxDynamicSharedMemorySize, GEMM_LN_SMEM);
    cudaFuncSetAttribute((const void*)tc_gemm_ln<true, false>,
                         cudaFuncAttributeMaxDynamicSharedMemorySize, GEMM_LN_SMEM);
    cudaFuncSetAttribute((const void*)tc_gemm_ln<false, false>,
                         cudaFuncAttributeMaxDynamicSharedMemorySize, GEMM_LN_SMEM);

    const int M = NTOK;
    const int mTiles = cdiv(M, 64);
    dim3 g256(2, mTiles), gHead(5, mTiles), g1024(8, mTiles);
    const int nAct4 = M * D_MODEL / 4;

    // 1: weight conversions (batched)
    WJobs J;
    J.j[0] = {vp_w, vpw, 65536 / 4};
    J.j[1] = {so_w, sow, 65536 / 4};
    J.j[2] = {aw_w, aww, 32768 / 4};
    J.j[3] = {op_w, opw, 65536 / 4};
    J.j[4] = {ipw,  wqw, 65536 / 4};
    J.j[5] = {mo_w, mow, 65536 / 4};
    J.j[6] = {l1_w, l1w, 262144 / 4};
    J.j[7] = {l2_w, l2w, 262144 / 4};
    int totW4 = (65536 * 5 + 32768 + 262144 * 2) / 4;
    wconv_kernel<<<cdiv(totW4, 256), 256>>>(J);
    // 2: activation conversions (src -> A, src+pos -> B)
    actconv_kernel<<<cdiv(nAct4, 256), 256>>>(src, pos, A, B, nAct4);
    // 3: text K/V (fp16)
    kv_proj_kernel<<<B_SZ * LT, 256>>>(text, ipw, ipb, kh, vh);
    // 4: FUSED head GEMMs: val (fp16) + offs + aw (softmax16)
    tc_gemm_head<<<gHead, 256, GEMM_SMEM>>>(A, B, vpw, sow, aww, vp_b, so_b, aw_b,
                                            val, offs, aw, M);
    // 5: deformable sampling -> ms (fp16, into A)
    msdeform_kernel<<<cdiv(M * NH * 32, 256), 256>>>(val, offs, aw, refp, A);
    // 6: fused GEMM+LN1: x = LN(ms@op^T + b + src) -> out_x; (x+pos) -> B
    tc_gemm_ln<true, true><<<mTiles, 256, GEMM_LN_SMEM>>>(A, opw, op_b, src,
                                                          ln1_g, ln1_b, pos, out_x, B,
                                                          M, 256);
    // 7: qh = (x+pos) @ wq^T + bq -> fp16
    tc_gemm<0, true><<<g256, 256, GEMM_SMEM>>>(B, wqw, ipb, (float*)q, M, 256, 256);
    // 8: cross attention (smem k/v) -> ctx (fp16, into A)
    cross_attn_kernel<<<cdiv(M * NH, 256), 256>>>(q, kh, vh, A);
    // 9: fused GEMM+LN3: x = LN(ctx@mo^T + b + x) -> out_x; x -> B
    tc_gemm_ln<true, false><<<mTiles, 256, GEMM_LN_SMEM>>>(A, mow, mo_b, out_x,
                                                           ln3_g, ln3_b, nullptr, out_x, B,
                                                           M, 256);
    // 10: hid = relu(x@l1^T + b1) -> fp16
    tc_gemm<2, true><<<g1024, 256, GEMM_SMEM>>>(B, l1w, l1_b, (float*)hid, M, DFF, 256);
    // 11: fused GEMM+LN2: out = LN(hid@l2^T + b2 + x) -> out_x
    tc_gemm_ln<false, false><<<mTiles, 256, GEMM_LN_SMEM>>>(hid, l2w, l2_b, out_x,
                                                            ln2_g, ln2_b, nullptr, out_x,
                                                            nullptr, M, 1024);
    // 12: pass-through text_memory
    cudaMemcpyAsync(out_text, text, (size_t)B_SZ * LT * D_MODEL * sizeof(float),
                    cudaMemcpyDeviceToDevice, 0);
}